// round 4
// baseline (speedup 1.0000x reference)
#include <cuda_runtime.h>

// ---------------------------------------------------------------------------
// MaskRemoval — R4: latency-focused rewrite, single stream.
//   k_sort    : rank sort + per-class ROI lists (1 CTA, probs staged in smem)
//   k_bits    : parallel per-ROI rasterization -> bit words + msum
//               (2 CTAs per ROI, warp-ballot)
//   k_scan    : one CTA/class, loops ONLY its own ROIs; class mask in 80KB
//               dynamic smem; ROI bits cached in registers between passes
//   k_compact : prefix scan -> slot table + keep_inds
//   k_zero    : 256MB streaming zero (__stcs, x4 unroll)
//   k_paste   : bilinear values inside kept boxes (2 CTAs per slot)
// ---------------------------------------------------------------------------

#define MAXN   128
#define NCLS   80
#define MM     28
#define IMG_H  800
#define IMG_W  800
#define WPR    ((IMG_W + 31) / 32)     // 25 words per image row
#define BOXMAX 384
#define BITSW  8192                    // words of bit-scratch per ROI
#define CMASK_BYTES (IMG_H * WPR * 4)  // 80000 B dynamic smem for k_scan

__device__ int g_order[MAXN];
__device__ int g_bx0[MAXN], g_by0[MAXN];
__device__ int g_bx1[MAXN], g_by1[MAXN];
__device__ int g_keep[MAXN];
__device__ int g_slot[MAXN];
__device__ int g_msum[MAXN];
__device__ int g_ccount[NCLS];
__device__ int g_clist[NCLS][MAXN];
__device__ unsigned int g_bits[MAXN][BITSW];          // 4 MB ROI bit rasters

// ---------------------------------------------------------------------------
__global__ __launch_bounds__(128) void k_sort(const float* __restrict__ rois,
                                              const float* __restrict__ prob,
                                              const int*   __restrict__ clsidx,
                                              int N) {
    __shared__ float sp[MAXN];
    __shared__ int   scls[MAXN];       // class of sorted index i
    int i = threadIdx.x;
    if (i < N) sp[i] = prob[i];
    if (i < MAXN) { g_keep[i] = 0; g_msum[i] = 0; }
    if (i < NCLS) g_ccount[i] = 0;
    __syncthreads();

    if (i < N) {
        float pi = sp[i];
        int r = 0;
        for (int j = 0; j < N; j++) {
            float pj = sp[j];
            r += (pj > pi) || (pj == pi && j < i);    // stable descending rank
        }
        g_order[r] = i;
    }
    __syncthreads();
    if (i < N) {
        int o = g_order[i];
        g_bx0[i] = (int)rois[4 * o + 0];   // trunc-toward-zero == astype(int32)
        g_by0[i] = (int)rois[4 * o + 1];
        g_bx1[i] = (int)rois[4 * o + 2];
        g_by1[i] = (int)rois[4 * o + 3];
        scls[i] = clsidx[o] - 1;
    }
    __syncthreads();
    // per-class lists in sorted order (serial over N on smem: cheap)
    if (i == 0) {
        for (int s = 0; s < N; s++) {
            int c = scls[s];
            if (c >= 0 && c < NCLS) g_clist[c][g_ccount[c]++] = s;
        }
    }
}

// exact reference bilinear form (keep decision thresholds on val>0)
__device__ __forceinline__ float bilin_ref(const float* lg, float sx, float sy) {
    int ix0 = (int)sx;
    int iy0 = (int)sy;
    int ix1 = min(ix0 + 1, MM - 1);
    int iy1 = min(iy0 + 1, MM - 1);
    float fx = sx - (float)ix0;
    float fy = sy - (float)iy0;
    float v00 = lg[iy0 * MM + ix0], v01 = lg[iy0 * MM + ix1];
    float v10 = lg[iy1 * MM + ix0], v11 = lg[iy1 * MM + ix1];
    return (1.0f - fy) * ((1.0f - fx) * v00 + fx * v01)
         +         fy  * ((1.0f - fx) * v10 + fx * v11);
}

// ---------------------------------------------------------------------------
// Parallel rasterization: grid (N, 2); blockIdx.y picks a y-half of the box.
__global__ __launch_bounds__(256) void k_bits(const float* __restrict__ mask_prob,
                                              int N) {
    int i = blockIdx.x;
    if (i >= N) return;

    __shared__ float lg[MM * MM];
    __shared__ int   s_ix0[BOXMAX], s_ix1[BOXMAX];
    __shared__ float s_fx[BOXMAX];
    __shared__ int   s_cnt;

    int x0 = g_bx0[i], y0 = g_by0[i], x1 = g_bx1[i], y1 = g_by1[i];
    int xs0 = max(x0, 0), xs1 = min(x1 + 1, IMG_W);
    int ys0 = max(y0, 0), ys1 = min(y1 + 1, IMG_H);
    int bw = xs1 - xs0, bh = ys1 - ys0;
    if (bw <= 0 || bh <= 0) return;      // msum already 0

    if (threadIdx.x == 0) s_cnt = 0;

    int o = g_order[i];
    const float* lp = mask_prob + (long long)o * (MM * MM);
    for (int t = threadIdx.x; t < MM * MM; t += blockDim.x) lg[t] = lp[t];

    float wv = fmaxf((float)(x1 - x0 + 1), 1.0f);
    float hv = fmaxf((float)(y1 - y0 + 1), 1.0f);
    float scx = 28.0f / wv, scy = 28.0f / hv;

    bool pre = (bw <= BOXMAX);
    if (pre) {
        for (int t = threadIdx.x; t < bw; t += blockDim.x) {
            float sx = fminf(fmaxf(((float)(xs0 + t) - (float)x0 + 0.5f) * scx - 0.5f, 0.0f), 27.0f);
            int ix0 = (int)sx;
            s_ix0[t] = ix0;
            s_ix1[t] = min(ix0 + 1, MM - 1);
            s_fx[t]  = sx - (float)ix0;
        }
    }
    __syncthreads();

    int xw0 = xs0 >> 5, xw1 = (xs1 + 31) >> 5;
    int nwx = xw1 - xw0;
    bool fits = (nwx * bh <= BITSW);

    // y-half handled by this CTA
    int half = (bh + 1) >> 1;
    int ry0  = blockIdx.y * half;
    int rows = min(half, bh - ry0);
    if (rows <= 0) return;
    int cnt = nwx * rows;

    int warp = threadIdx.x >> 5;
    int lane = threadIdx.x & 31;
    int nwarps = blockDim.x >> 5;
    int lm = 0;

    for (int k = warp; k < cnt; k += nwarps) {
        int ry = ry0 + k / nwx;
        int xw = xw0 + (k - (k / nwx) * nwx);
        int y  = ys0 + ry;
        int x  = (xw << 5) + lane;
        bool on = false;
        if (x >= xs0 && x < xs1) {
            float sy = fminf(fmaxf(((float)y - (float)y0 + 0.5f) * scy - 0.5f, 0.0f), 27.0f);
            int iy0 = (int)sy;
            int iy1 = min(iy0 + 1, MM - 1);
            float fy = sy - (float)iy0;
            const float* r0 = lg + iy0 * MM;
            const float* r1 = lg + iy1 * MM;
            float val;
            if (pre) {
                int col = x - xs0;
                int ix0 = s_ix0[col], ix1 = s_ix1[col];
                float fx = s_fx[col];
                val = (1.0f - fy) * ((1.0f - fx) * r0[ix0] + fx * r0[ix1])
                    +         fy  * ((1.0f - fx) * r1[ix0] + fx * r1[ix1]);
            } else {
                float sx = fminf(fmaxf(((float)x - (float)x0 + 0.5f) * scx - 0.5f, 0.0f), 27.0f);
                val = bilin_ref(lg, sx, sy);
            }
            on = (val > 0.0f);
        }
        unsigned int bits = __ballot_sync(0xffffffffu, on);
        if (lane == 0) {
            if (fits) g_bits[i][ry * nwx + (xw - xw0)] = bits;
            lm += __popc(bits);
        }
    }
    if (lane == 0 && lm) atomicAdd(&s_cnt, lm);
    __syncthreads();
    if (threadIdx.x == 0 && s_cnt) atomicAdd(&g_msum[i], s_cnt);
}

// ---------------------------------------------------------------------------
// Per-class suppression: class mask in dynamic shared memory, short ROI list.
__global__ __launch_bounds__(256) void k_scan(const float* __restrict__ mask_prob,
                                              int N) {
    int c = blockIdx.x;
    int nc = g_ccount[c];
    if (nc == 0) return;

    extern __shared__ unsigned int sm_mask[];          // IMG_H*WPR words
    __shared__ int s_ovl, s_keep;
    __shared__ float lg[MM * MM];

    for (int w = threadIdx.x; w < IMG_H * WPR; w += blockDim.x) sm_mask[w] = 0u;
    __syncthreads();

    for (int j = 0; j < nc; j++) {
        int i = g_clist[c][j];
        int msum = g_msum[i];
        if (msum == 0) { if (threadIdx.x == 0) g_keep[i] = 0; continue; }

        int x0 = g_bx0[i], y0 = g_by0[i], x1 = g_bx1[i], y1 = g_by1[i];
        int xs0 = max(x0, 0), xs1 = min(x1 + 1, IMG_W);
        int ys0 = max(y0, 0), ys1 = min(y1 + 1, IMG_H);
        int bh = ys1 - ys0;

        int xw0 = xs0 >> 5, xw1 = (xs1 + 31) >> 5;
        int nwx = xw1 - xw0;
        int total = nwx * bh;
        bool fits = (total <= BITSW);

        if (threadIdx.x == 0) s_ovl = 0;
        __syncthreads();

        int lo = 0;
        unsigned int cb[BITSW / 256 + 1];              // register cache of bits
        if (fits) {
            const unsigned int* bi = g_bits[i];
            int t = 0;
            for (int k = threadIdx.x; k < total; k += blockDim.x, t++) {
                unsigned int b = bi[k];
                cb[t] = b;
                if (b) {
                    int ry = k / nwx;
                    int xw = xw0 + (k - ry * nwx);
                    lo += __popc(b & sm_mask[(ys0 + ry) * WPR + xw]);
                }
            }
        } else {
            int o = g_order[i];
            const float* lp = mask_prob + (long long)o * (MM * MM);
            for (int t = threadIdx.x; t < MM * MM; t += blockDim.x) lg[t] = lp[t];
            __syncthreads();
            float wv = fmaxf((float)(x1 - x0 + 1), 1.0f);
            float hv = fmaxf((float)(y1 - y0 + 1), 1.0f);
            float scx = 28.0f / wv, scy = 28.0f / hv;
            for (int k = threadIdx.x; k < total; k += blockDim.x) {
                int ry = k / nwx;
                int y  = ys0 + ry;
                int xw = xw0 + (k - ry * nwx);
                float sy = fminf(fmaxf(((float)y - (float)y0 + 0.5f) * scy - 0.5f, 0.0f), 27.0f);
                int xlo2 = max(xs0, xw << 5);
                int xhi2 = min(xs1, (xw << 5) + 32);
                unsigned int cw = sm_mask[y * WPR + xw];
                for (int x = xlo2; x < xhi2; x++) {
                    if (cw & (1u << (x & 31))) {
                        float sx = fminf(fmaxf(((float)x - (float)x0 + 0.5f) * scx - 0.5f, 0.0f), 27.0f);
                        if (bilin_ref(lg, sx, sy) > 0.0f) lo++;
                    }
                }
            }
        }
        #pragma unroll
        for (int off = 16; off > 0; off >>= 1)
            lo += __shfl_down_sync(0xffffffffu, lo, off);
        if ((threadIdx.x & 31) == 0 && lo) atomicAdd(&s_ovl, lo);
        __syncthreads();

        if (threadIdx.x == 0) {
            int kp = ((float)s_ovl <= 0.3f * (float)msum);
            s_keep = kp;
            g_keep[i] = kp;
        }
        __syncthreads();

        if (s_keep) {
            if (fits) {
                int t = 0;
                for (int k = threadIdx.x; k < total; k += blockDim.x, t++) {
                    unsigned int b = cb[t];
                    if (b) {
                        int ry = k / nwx;
                        int xw = xw0 + (k - ry * nwx);
                        sm_mask[(ys0 + ry) * WPR + xw] |= b;
                    }
                }
            } else {
                float wv = fmaxf((float)(x1 - x0 + 1), 1.0f);
                float hv = fmaxf((float)(y1 - y0 + 1), 1.0f);
                float scx = 28.0f / wv, scy = 28.0f / hv;
                for (int k = threadIdx.x; k < total; k += blockDim.x) {
                    int ry = k / nwx;
                    int y  = ys0 + ry;
                    int xw = xw0 + (k - ry * nwx);
                    float sy = fminf(fmaxf(((float)y - (float)y0 + 0.5f) * scy - 0.5f, 0.0f), 27.0f);
                    int xlo2 = max(xs0, xw << 5);
                    int xhi2 = min(xs1, (xw << 5) + 32);
                    unsigned int bits = 0u;
                    for (int x = xlo2; x < xhi2; x++) {
                        float sx = fminf(fmaxf(((float)x - (float)x0 + 0.5f) * scx - 0.5f, 0.0f), 27.0f);
                        if (bilin_ref(lg, sx, sy) > 0.0f) bits |= (1u << (x & 31));
                    }
                    if (bits) sm_mask[y * WPR + xw] |= bits;
                }
            }
        }
        __syncthreads();
    }
}

// ---------------------------------------------------------------------------
__global__ __launch_bounds__(128) void k_compact(float* __restrict__ out_keep,
                                                 int N, int has_keep) {
    __shared__ int pf[128];
    int i = threadIdx.x;
    int k = (i < N) ? g_keep[i] : 0;
    pf[i] = k;
    __syncthreads();
    #pragma unroll
    for (int off = 1; off < 128; off <<= 1) {
        int v = (i >= off) ? pf[i - off] : 0;
        __syncthreads();
        pf[i] += v;
        __syncthreads();
    }
    if (i < N) g_slot[i] = -1;
    __syncthreads();
    if (i < N && k) g_slot[pf[i] - 1] = i;
    __syncthreads();
    if (has_keep && i < N) {
        int s = g_slot[i];
        out_keep[i] = (s >= 0) ? (float)g_order[s] : -1.0f;
    }
}

// ---------------------------------------------------------------------------
__global__ __launch_bounds__(256) void k_zero(float4* __restrict__ p, long long n4) {
    long long base = ((long long)blockIdx.x * blockDim.x + threadIdx.x) * 4;
    long long stride = (long long)gridDim.x * blockDim.x * 4;
    float4 z = make_float4(0.f, 0.f, 0.f, 0.f);
    for (long long i = base; i + 3 < n4; i += stride) {
        __stcs(&p[i],     z);
        __stcs(&p[i + 1], z);
        __stcs(&p[i + 2], z);
        __stcs(&p[i + 3], z);
    }
    // tail (n4 is a multiple of 4 for these shapes, but stay safe)
    long long rem = n4 & ~3LL;
    for (long long i = rem + base / 4; i < n4; i += stride / 4) __stcs(&p[i], z);
}

// ---------------------------------------------------------------------------
// grid (N, 2): blockIdx.y picks a y-half of the kept box.
__global__ __launch_bounds__(256) void k_paste(const float* __restrict__ mask_prob,
                                               float* __restrict__ energy) {
    int slot = blockIdx.x;
    int s = g_slot[slot];
    if (s < 0) return;

    __shared__ float lg[MM * MM];
    int o = g_order[s];
    const float* lp = mask_prob + (long long)o * (MM * MM);
    for (int t = threadIdx.x; t < MM * MM; t += blockDim.x) lg[t] = lp[t];
    __syncthreads();

    int x0 = g_bx0[s], y0 = g_by0[s], x1 = g_bx1[s], y1 = g_by1[s];
    int xs0 = max(x0, 0), xs1 = min(x1 + 1, IMG_W);
    int ys0 = max(y0, 0), ys1 = min(y1 + 1, IMG_H);
    int bw = xs1 - xs0, bh = ys1 - ys0;
    if (bw <= 0 || bh <= 0) return;

    int half = (bh + 1) >> 1;
    int ry0  = blockIdx.y * half;
    int rows = min(half, bh - ry0);
    if (rows <= 0) return;

    float wv = fmaxf((float)(x1 - x0 + 1), 1.0f);
    float hv = fmaxf((float)(y1 - y0 + 1), 1.0f);
    float scx = 28.0f / wv, scy = 28.0f / hv;

    float* base = energy + (long long)slot * IMG_H * IMG_W;
    int total = bw * rows;
    for (int k = threadIdx.x; k < total; k += blockDim.x) {
        int ry = ry0 + k / bw;
        int rx = k - (k / bw) * bw;
        int y = ys0 + ry, x = xs0 + rx;
        float sy = fminf(fmaxf(((float)y - (float)y0 + 0.5f) * scy - 0.5f, 0.0f), 27.0f);
        float sx = fminf(fmaxf(((float)x - (float)x0 + 0.5f) * scx - 0.5f, 0.0f), 27.0f);
        base[y * IMG_W + x] = bilin_ref(lg, sx, sy);
    }
}

// ---------------------------------------------------------------------------
extern "C" void kernel_launch(void* const* d_in, const int* in_sizes, int n_in,
                              void* d_out, int out_size) {
    const float* rois  = (const float*)d_in[0];
    const float* prob  = (const float*)d_in[1];
    const float* mp    = (const float*)d_in[2];
    const int*   cidx  = (const int*)d_in[3];

    int N = in_sizes[1];
    if (N > MAXN) N = MAXN;

    float* out = (float*)d_out;
    long long HW = (long long)IMG_H * IMG_W;
    int has_keep = ((long long)out_size == (long long)N + (long long)N * HW) ? 1 : 0;
    float* energy = out + (has_keep ? N : 0);
    long long n4 = ((long long)N * HW) / 4;

    cudaFuncSetAttribute(k_scan, cudaFuncAttributeMaxDynamicSharedMemorySize,
                         CMASK_BYTES);

    k_sort<<<1, 128>>>(rois, prob, cidx, N);
    k_bits<<<dim3(N, 2), 256>>>(mp, N);
    k_scan<<<NCLS, 256, CMASK_BYTES>>>(mp, N);
    k_compact<<<1, 128>>>(out, N, has_keep);
    k_zero<<<2048, 256>>>((float4*)energy, n4);
    k_paste<<<dim3(N, 2), 256>>>(mp, energy);
}

// round 5
// speedup vs baseline: 1.0915x; 1.0915x over previous
#include <cuda_runtime.h>

// ---------------------------------------------------------------------------
// MaskRemoval — R5: 3 self-staging kernels + memset, fork-join overlap.
//
//   memset   : 256MB zero of energy (side stream, overlapped with chain)
//   k_bits   : grid (N,2). Each CTA recomputes the rank sort in smem, then
//              rasterizes its (sorted ROI, y-half) via warp ballot into
//              g_bits + per-half popcount (no atomics across CTAs).
//   k_scan   : grid (NCLS). Self-staging sort + class list from smem; class
//              mask in 80KB dynamic smem; popc overlap + OR merge using
//              g_bits cached in registers between the two passes.
//   k_paste  : grid (N+1,2). Self-staging sort + smem prefix over g_keep
//              gives each CTA its output slot; CTA N writes keep_inds.
// ---------------------------------------------------------------------------

#define MAXN   128
#define NCLS   80
#define MM     28
#define IMG_H  800
#define IMG_W  800
#define WPR    25                      // 800/32 words per image row
#define BOXMAX 384
#define BITSW  8192                    // words of bit-scratch per ROI
#define CMASK_BYTES (IMG_H * WPR * 4)  // 80000 B dynamic smem for k_scan

__device__ int g_keep[MAXN];
__device__ int g_msum2[MAXN][2];                 // per-half popcounts
__device__ unsigned int g_bits[MAXN][BITSW];     // 4 MB ROI bit rasters

// exact reference bilinear form (keep decision thresholds on val>0)
__device__ __forceinline__ float bilin_ref(const float* lg, float sx, float sy) {
    int ix0 = (int)sx;
    int iy0 = (int)sy;
    int ix1 = min(ix0 + 1, MM - 1);
    int iy1 = min(iy0 + 1, MM - 1);
    float fx = sx - (float)ix0;
    float fy = sy - (float)iy0;
    float v00 = lg[iy0 * MM + ix0], v01 = lg[iy0 * MM + ix1];
    float v10 = lg[iy1 * MM + ix0], v11 = lg[iy1 * MM + ix1];
    return (1.0f - fy) * ((1.0f - fx) * v00 + fx * v01)
         +         fy  * ((1.0f - fx) * v10 + fx * v11);
}

// stable descending rank sort into smem: sord[rank] = original index
__device__ __forceinline__ void stage_sort(const float* __restrict__ prob,
                                           int N, float* sp, int* sord) {
    int t = threadIdx.x;
    if (t < N) sp[t] = prob[t];
    __syncthreads();
    if (t < N) {
        float pi = sp[t];
        int r = 0;
        for (int j = 0; j < N; j++) {
            float pj = sp[j];
            r += (pj > pi) || (pj == pi && j < t);
        }
        sord[r] = t;
    }
    __syncthreads();
}

// ---------------------------------------------------------------------------
__global__ __launch_bounds__(256) void k_bits(const float* __restrict__ rois,
                                              const float* __restrict__ prob,
                                              const float* __restrict__ mask_prob,
                                              int N) {
    __shared__ float sp[MAXN];
    __shared__ int   sord[MAXN];
    __shared__ float lg[MM * MM];
    __shared__ int   s_ix0[BOXMAX], s_ix1[BOXMAX];
    __shared__ float s_fx[BOXMAX];
    __shared__ int   s_cnt;

    int i = blockIdx.x;
    if (i >= N) return;
    stage_sort(prob, N, sp, sord);

    int o = sord[i];
    float4 rb = reinterpret_cast<const float4*>(rois)[o];
    int x0 = (int)rb.x, y0 = (int)rb.y, x1 = (int)rb.z, y1 = (int)rb.w;
    int xs0 = max(x0, 0), xs1 = min(x1 + 1, IMG_W);
    int ys0 = max(y0, 0), ys1 = min(y1 + 1, IMG_H);
    int bw = xs1 - xs0, bh = ys1 - ys0;
    if (bw <= 0 || bh <= 0) return;        // g_msum2 stays 0

    if (threadIdx.x == 0) s_cnt = 0;
    const float* lp = mask_prob + (long long)o * (MM * MM);
    for (int t = threadIdx.x; t < MM * MM; t += blockDim.x) lg[t] = lp[t];

    float wv = fmaxf((float)(x1 - x0 + 1), 1.0f);
    float hv = fmaxf((float)(y1 - y0 + 1), 1.0f);
    float scx = 28.0f / wv, scy = 28.0f / hv;

    bool pre = (bw <= BOXMAX);
    if (pre) {
        for (int t = threadIdx.x; t < bw; t += blockDim.x) {
            float sx = fminf(fmaxf(((float)(xs0 + t) - (float)x0 + 0.5f) * scx - 0.5f, 0.0f), 27.0f);
            int ix0 = (int)sx;
            s_ix0[t] = ix0;
            s_ix1[t] = min(ix0 + 1, MM - 1);
            s_fx[t]  = sx - (float)ix0;
        }
    }
    __syncthreads();

    int xw0 = xs0 >> 5, xw1 = (xs1 + 31) >> 5;
    int nwx = xw1 - xw0;
    bool fits = (nwx * bh <= BITSW);

    int half = (bh + 1) >> 1;
    int ry0  = blockIdx.y * half;
    int rows = min(half, bh - ry0);
    if (rows <= 0) return;                 // half stays 0 in g_msum2
    int cnt = nwx * rows;

    int warp = threadIdx.x >> 5;
    int lane = threadIdx.x & 31;
    int nwarps = blockDim.x >> 5;
    int lm = 0;

    for (int k = warp; k < cnt; k += nwarps) {
        int q  = k / nwx;
        int ry = ry0 + q;
        int xw = xw0 + (k - q * nwx);
        int y  = ys0 + ry;
        int x  = (xw << 5) + lane;
        bool on = false;
        if (x >= xs0 && x < xs1) {
            float sy = fminf(fmaxf(((float)y - (float)y0 + 0.5f) * scy - 0.5f, 0.0f), 27.0f);
            int iy0 = (int)sy;
            int iy1 = min(iy0 + 1, MM - 1);
            float fy = sy - (float)iy0;
            const float* r0 = lg + iy0 * MM;
            const float* r1 = lg + iy1 * MM;
            float val;
            if (pre) {
                int col = x - xs0;
                int ix0 = s_ix0[col], ix1 = s_ix1[col];
                float fx = s_fx[col];
                val = (1.0f - fy) * ((1.0f - fx) * r0[ix0] + fx * r0[ix1])
                    +         fy  * ((1.0f - fx) * r1[ix0] + fx * r1[ix1]);
            } else {
                float sx = fminf(fmaxf(((float)x - (float)x0 + 0.5f) * scx - 0.5f, 0.0f), 27.0f);
                val = bilin_ref(lg, sx, sy);
            }
            on = (val > 0.0f);
        }
        unsigned int bits = __ballot_sync(0xffffffffu, on);
        if (lane == 0) {
            if (fits) g_bits[i][ry * nwx + (xw - xw0)] = bits;
            lm += __popc(bits);
        }
    }
    if (lane == 0 && lm) atomicAdd(&s_cnt, lm);
    __syncthreads();
    if (threadIdx.x == 0) g_msum2[i][blockIdx.y] = s_cnt;   // overwrite, no zeroing
}

// ---------------------------------------------------------------------------
__global__ __launch_bounds__(256) void k_scan(const float* __restrict__ rois,
                                              const float* __restrict__ prob,
                                              const int*   __restrict__ clsidx,
                                              const float* __restrict__ mask_prob,
                                              int N) {
    extern __shared__ unsigned int sm_mask[];               // IMG_H*WPR words
    __shared__ float sp[MAXN];
    __shared__ int   sord[MAXN];
    __shared__ int   scls[MAXN];
    __shared__ int   s_ovl, s_keep;
    __shared__ float lg[MM * MM];

    int c = blockIdx.x;
    int t = threadIdx.x;

    // self-staging sort + class per sorted slot
    if (t < N) sp[t] = prob[t];
    __syncthreads();
    if (t < N) {
        float pi = sp[t];
        int r = 0;
        for (int j = 0; j < N; j++) {
            float pj = sp[j];
            r += (pj > pi) || (pj == pi && j < t);
        }
        sord[r] = t;
        scls[r] = clsidx[t] - 1;
    }
    __syncthreads();

    // zero the class mask (uint4 stores)
    uint4* m4 = reinterpret_cast<uint4*>(sm_mask);
    uint4 z4 = make_uint4(0u, 0u, 0u, 0u);
    for (int w = t; w < (IMG_H * WPR) / 4; w += blockDim.x) m4[w] = z4;
    __syncthreads();

    for (int i = 0; i < N; i++) {
        if (scls[i] != c) continue;                       // uniform (smem)

        int msum = g_msum2[i][0] + g_msum2[i][1];
        if (msum == 0) { if (t == 0) g_keep[i] = 0; continue; }

        int o = sord[i];
        float4 rb = reinterpret_cast<const float4*>(rois)[o];
        int x0 = (int)rb.x, y0 = (int)rb.y, x1 = (int)rb.z, y1 = (int)rb.w;
        int xs0 = max(x0, 0), xs1 = min(x1 + 1, IMG_W);
        int ys0 = max(y0, 0), ys1 = min(y1 + 1, IMG_H);
        int bh = ys1 - ys0;

        int xw0 = xs0 >> 5, xw1 = (xs1 + 31) >> 5;
        int nwx = xw1 - xw0;
        int total = nwx * bh;
        bool fits = (total <= BITSW);

        if (t == 0) s_ovl = 0;
        __syncthreads();

        int lo = 0;
        unsigned int cb[BITSW / 256 + 1];                 // register bit cache
        if (fits) {
            const unsigned int* bi = g_bits[i];
            int u = 0;
            for (int k = t; k < total; k += blockDim.x, u++) {
                unsigned int b = bi[k];
                cb[u] = b;
                if (b) {
                    int ry = k / nwx;
                    int xw = xw0 + (k - ry * nwx);
                    lo += __popc(b & sm_mask[(ys0 + ry) * WPR + xw]);
                }
            }
        } else {
            const float* lp = mask_prob + (long long)o * (MM * MM);
            for (int u = t; u < MM * MM; u += blockDim.x) lg[u] = lp[u];
            __syncthreads();
            float wv = fmaxf((float)(x1 - x0 + 1), 1.0f);
            float hv = fmaxf((float)(y1 - y0 + 1), 1.0f);
            float scx = 28.0f / wv, scy = 28.0f / hv;
            for (int k = t; k < total; k += blockDim.x) {
                int ry = k / nwx;
                int y  = ys0 + ry;
                int xw = xw0 + (k - ry * nwx);
                unsigned int cw = sm_mask[y * WPR + xw];
                if (!cw) continue;
                float sy = fminf(fmaxf(((float)y - (float)y0 + 0.5f) * scy - 0.5f, 0.0f), 27.0f);
                int xlo2 = max(xs0, xw << 5);
                int xhi2 = min(xs1, (xw << 5) + 32);
                for (int x = xlo2; x < xhi2; x++) {
                    if (cw & (1u << (x & 31))) {
                        float sx = fminf(fmaxf(((float)x - (float)x0 + 0.5f) * scx - 0.5f, 0.0f), 27.0f);
                        if (bilin_ref(lg, sx, sy) > 0.0f) lo++;
                    }
                }
            }
        }
        #pragma unroll
        for (int off = 16; off > 0; off >>= 1)
            lo += __shfl_down_sync(0xffffffffu, lo, off);
        if ((t & 31) == 0 && lo) atomicAdd(&s_ovl, lo);
        __syncthreads();

        if (t == 0) {
            int kp = ((float)s_ovl <= 0.3f * (float)msum);
            s_keep = kp;
            g_keep[i] = kp;
        }
        __syncthreads();

        if (s_keep) {
            if (fits) {
                int u = 0;
                for (int k = t; k < total; k += blockDim.x, u++) {
                    unsigned int b = cb[u];
                    if (b) {
                        int ry = k / nwx;
                        int xw = xw0 + (k - ry * nwx);
                        sm_mask[(ys0 + ry) * WPR + xw] |= b;
                    }
                }
            } else {
                float wv = fmaxf((float)(x1 - x0 + 1), 1.0f);
                float hv = fmaxf((float)(y1 - y0 + 1), 1.0f);
                float scx = 28.0f / wv, scy = 28.0f / hv;
                for (int k = t; k < total; k += blockDim.x) {
                    int ry = k / nwx;
                    int y  = ys0 + ry;
                    int xw = xw0 + (k - ry * nwx);
                    float sy = fminf(fmaxf(((float)y - (float)y0 + 0.5f) * scy - 0.5f, 0.0f), 27.0f);
                    int xlo2 = max(xs0, xw << 5);
                    int xhi2 = min(xs1, (xw << 5) + 32);
                    unsigned int bits = 0u;
                    for (int x = xlo2; x < xhi2; x++) {
                        float sx = fminf(fmaxf(((float)x - (float)x0 + 0.5f) * scx - 0.5f, 0.0f), 27.0f);
                        if (bilin_ref(lg, sx, sy) > 0.0f) bits |= (1u << (x & 31));
                    }
                    if (bits) sm_mask[y * WPR + xw] |= bits;
                }
            }
        }
        __syncthreads();
    }
}

// ---------------------------------------------------------------------------
// grid (N+1, 2): CTAs [0,N) paste their kept box half; CTA N writes keep_inds.
__global__ __launch_bounds__(256) void k_paste(const float* __restrict__ rois,
                                               const float* __restrict__ prob,
                                               const float* __restrict__ mask_prob,
                                               float* __restrict__ out_keep,
                                               float* __restrict__ energy,
                                               int N, int has_keep) {
    __shared__ float sp[MAXN];
    __shared__ int   sord[MAXN];
    __shared__ int   kv[MAXN];
    __shared__ int   pf[MAXN];
    __shared__ float lg[MM * MM];

    int t = threadIdx.x;
    stage_sort(prob, N, sp, sord);

    if (t < MAXN) {
        int k = (t < N) ? g_keep[t] : 0;
        kv[t] = k;
        pf[t] = k;
    }
    __syncthreads();
    #pragma unroll
    for (int off = 1; off < MAXN; off <<= 1) {
        int v = (t < MAXN && t >= off) ? pf[t - off] : 0;
        __syncthreads();
        if (t < MAXN) pf[t] += v;
        __syncthreads();
    }

    int i = blockIdx.x;
    if (i >= N) {                          // keep_inds writer
        if (blockIdx.y != 0 || !has_keep) return;
        int nk = pf[N - 1];
        if (t < N) {
            if (kv[t]) out_keep[pf[t] - 1] = (float)sord[t];
            if (t >= nk) out_keep[t] = -1.0f;
        }
        return;
    }

    if (!kv[i]) return;
    int slot = pf[i] - 1;

    int o = sord[i];
    float4 rb = reinterpret_cast<const float4*>(rois)[o];
    int x0 = (int)rb.x, y0 = (int)rb.y, x1 = (int)rb.z, y1 = (int)rb.w;
    int xs0 = max(x0, 0), xs1 = min(x1 + 1, IMG_W);
    int ys0 = max(y0, 0), ys1 = min(y1 + 1, IMG_H);
    int bw = xs1 - xs0, bh = ys1 - ys0;
    if (bw <= 0 || bh <= 0) return;

    const float* lp = mask_prob + (long long)o * (MM * MM);
    for (int u = t; u < MM * MM; u += blockDim.x) lg[u] = lp[u];
    __syncthreads();

    int half = (bh + 1) >> 1;
    int ry0  = blockIdx.y * half;
    int rows = min(half, bh - ry0);
    if (rows <= 0) return;

    float wv = fmaxf((float)(x1 - x0 + 1), 1.0f);
    float hv = fmaxf((float)(y1 - y0 + 1), 1.0f);
    float scx = 28.0f / wv, scy = 28.0f / hv;

    float* base = energy + (long long)slot * IMG_H * IMG_W;
    int total = bw * rows;
    for (int k = t; k < total; k += blockDim.x) {
        int q  = k / bw;
        int ry = ry0 + q;
        int rx = k - q * bw;
        int y = ys0 + ry, x = xs0 + rx;
        float sy = fminf(fmaxf(((float)y - (float)y0 + 0.5f) * scy - 0.5f, 0.0f), 27.0f);
        float sx = fminf(fmaxf(((float)x - (float)x0 + 0.5f) * scx - 0.5f, 0.0f), 27.0f);
        base[y * IMG_W + x] = bilin_ref(lg, sx, sy);
    }
}

// ---------------------------------------------------------------------------
extern "C" void kernel_launch(void* const* d_in, const int* in_sizes, int n_in,
                              void* d_out, int out_size) {
    const float* rois  = (const float*)d_in[0];
    const float* prob  = (const float*)d_in[1];
    const float* mp    = (const float*)d_in[2];
    const int*   cidx  = (const int*)d_in[3];

    int N = in_sizes[1];
    if (N > MAXN) N = MAXN;

    float* out = (float*)d_out;
    long long HW = (long long)IMG_H * IMG_W;
    int has_keep = ((long long)out_size == (long long)N + (long long)N * HW) ? 1 : 0;
    float* energy = out + (has_keep ? N : 0);

    static cudaStream_t s_side = nullptr;
    static cudaEvent_t ev_fork = nullptr, ev_join = nullptr;
    static bool attr_set = false;
    if (!s_side) {
        cudaStreamCreateWithFlags(&s_side, cudaStreamNonBlocking);
        cudaEventCreateWithFlags(&ev_fork, cudaEventDisableTiming);
        cudaEventCreateWithFlags(&ev_join, cudaEventDisableTiming);
    }
    if (!attr_set) {
        cudaFuncSetAttribute(k_scan, cudaFuncAttributeMaxDynamicSharedMemorySize,
                             CMASK_BYTES);
        attr_set = true;
    }

    // fork: 256MB memset overlaps the decision chain
    cudaEventRecord(ev_fork, 0);
    cudaStreamWaitEvent(s_side, ev_fork, 0);
    cudaMemsetAsync(energy, 0, (size_t)N * HW * sizeof(float), s_side);
    cudaEventRecord(ev_join, s_side);

    k_bits<<<dim3(N, 2), 256>>>(rois, prob, mp, N);
    k_scan<<<NCLS, 256, CMASK_BYTES>>>(rois, prob, cidx, mp, N);

    cudaStreamWaitEvent(0, ev_join, 0);
    k_paste<<<dim3(N + 1, 2), 256>>>(rois, prob, mp, out, energy, N, has_keep);
}

// round 6
// speedup vs baseline: 1.7249x; 1.5803x over previous
#include <cuda_runtime.h>

// ---------------------------------------------------------------------------
// MaskRemoval — R6: occupancy fix for the latency-bound raster kernels.
//   memset  : 256MB zero on side stream (overlaps bits+scan)
//   k_bits  : grid (N,8) self-staging sort + warp-ballot raster -> g_bits,
//             per-eighth popcounts (no atomics, no zeroing needed)
//   k_scan  : grid (NCLS); class mask in 80KB dyn smem; popc + OR merge,
//             bits re-read from L2 (no register cache)
//   k_paste : grid (N+1,8); smem prefix over g_keep gives slots; CTA N
//             writes keep_inds
// ---------------------------------------------------------------------------

#define MAXN   128
#define NCLS   80
#define MM     28
#define IMG_H  800
#define IMG_W  800
#define WPR    25                      // 800/32 words per image row
#define BOXMAX 384
#define NSPLIT 8                       // y-slices per ROI for raster kernels
#define BITSW  8192                    // words of bit-scratch per ROI
#define CMASK_BYTES (IMG_H * WPR * 4)  // 80000 B dynamic smem for k_scan

__device__ int g_keep[MAXN];
__device__ int g_msumP[MAXN][NSPLIT];            // per-slice popcounts
__device__ unsigned int g_bits[MAXN][BITSW];     // 4 MB ROI bit rasters

// exact reference bilinear form (keep decision thresholds on val>0)
__device__ __forceinline__ float bilin_ref(const float* lg, float sx, float sy) {
    int ix0 = (int)sx;
    int iy0 = (int)sy;
    int ix1 = min(ix0 + 1, MM - 1);
    int iy1 = min(iy0 + 1, MM - 1);
    float fx = sx - (float)ix0;
    float fy = sy - (float)iy0;
    float v00 = lg[iy0 * MM + ix0], v01 = lg[iy0 * MM + ix1];
    float v10 = lg[iy1 * MM + ix0], v11 = lg[iy1 * MM + ix1];
    return (1.0f - fy) * ((1.0f - fx) * v00 + fx * v01)
         +         fy  * ((1.0f - fx) * v10 + fx * v11);
}

// stable descending rank sort into smem: sord[rank] = original index
__device__ __forceinline__ void stage_sort(const float* __restrict__ prob,
                                           int N, float* sp, int* sord) {
    int t = threadIdx.x;
    if (t < N) sp[t] = prob[t];
    __syncthreads();
    if (t < N) {
        float pi = sp[t];
        int r = 0;
        for (int j = 0; j < N; j++) {
            float pj = sp[j];
            r += (pj > pi) || (pj == pi && j < t);
        }
        sord[r] = t;
    }
    __syncthreads();
}

// ---------------------------------------------------------------------------
__global__ __launch_bounds__(256) void k_bits(const float* __restrict__ rois,
                                              const float* __restrict__ prob,
                                              const float* __restrict__ mask_prob,
                                              int N) {
    __shared__ float sp[MAXN];
    __shared__ int   sord[MAXN];
    __shared__ float lg[MM * MM];
    __shared__ int   s_ix0[BOXMAX], s_ix1[BOXMAX];
    __shared__ float s_fx[BOXMAX];
    __shared__ int   s_iy0[64], s_iy1[64];
    __shared__ float s_fy[64];
    __shared__ int   s_cnt;

    int i = blockIdx.x;
    if (i >= N) return;
    stage_sort(prob, N, sp, sord);

    int o = sord[i];
    float4 rb = reinterpret_cast<const float4*>(rois)[o];
    int x0 = (int)rb.x, y0 = (int)rb.y, x1 = (int)rb.z, y1 = (int)rb.w;
    int xs0 = max(x0, 0), xs1 = min(x1 + 1, IMG_W);
    int ys0 = max(y0, 0), ys1 = min(y1 + 1, IMG_H);
    int bw = xs1 - xs0, bh = ys1 - ys0;
    if (bw <= 0 || bh <= 0) return;        // g_msumP slot never written => 0

    if (threadIdx.x == 0) s_cnt = 0;
    const float* lp = mask_prob + (long long)o * (MM * MM);
    for (int t = threadIdx.x; t < MM * MM; t += blockDim.x) lg[t] = lp[t];

    float wv = fmaxf((float)(x1 - x0 + 1), 1.0f);
    float hv = fmaxf((float)(y1 - y0 + 1), 1.0f);
    float scx = 28.0f / wv, scy = 28.0f / hv;

    // this CTA's y-slice
    int chunk = (bh + NSPLIT - 1) / NSPLIT;
    int ry0   = blockIdx.y * chunk;
    int rows  = min(chunk, bh - ry0);

    bool pre = (bw <= BOXMAX) && (rows <= 64);
    if (pre) {
        for (int t = threadIdx.x; t < bw; t += blockDim.x) {
            float sx = fminf(fmaxf(((float)(xs0 + t) - (float)x0 + 0.5f) * scx - 0.5f, 0.0f), 27.0f);
            int ix0 = (int)sx;
            s_ix0[t] = ix0;
            s_ix1[t] = min(ix0 + 1, MM - 1);
            s_fx[t]  = sx - (float)ix0;
        }
        for (int t = threadIdx.x; t < rows && rows > 0; t += blockDim.x) {
            float sy = fminf(fmaxf(((float)(ys0 + ry0 + t) - (float)y0 + 0.5f) * scy - 0.5f, 0.0f), 27.0f);
            int iy0 = (int)sy;
            s_iy0[t] = iy0;
            s_iy1[t] = min(iy0 + 1, MM - 1);
            s_fy[t]  = sy - (float)iy0;
        }
    }
    __syncthreads();
    if (rows <= 0) return;

    int xw0 = xs0 >> 5, xw1 = (xs1 + 31) >> 5;
    int nwx = xw1 - xw0;
    bool fits = (nwx * bh <= BITSW);
    int cnt = nwx * rows;

    int warp = threadIdx.x >> 5;
    int lane = threadIdx.x & 31;
    int nwarps = blockDim.x >> 5;
    int lm = 0;

    for (int k = warp; k < cnt; k += nwarps) {
        int q  = k / nwx;
        int ry = ry0 + q;
        int xw = xw0 + (k - q * nwx);
        int x  = (xw << 5) + lane;
        bool on = false;
        if (x >= xs0 && x < xs1) {
            float val;
            if (pre) {
                int col = x - xs0;
                int iy0 = s_iy0[q], iy1 = s_iy1[q];
                float fy = s_fy[q];
                int ix0 = s_ix0[col], ix1 = s_ix1[col];
                float fx = s_fx[col];
                const float* r0 = lg + iy0 * MM;
                const float* r1 = lg + iy1 * MM;
                val = (1.0f - fy) * ((1.0f - fx) * r0[ix0] + fx * r0[ix1])
                    +         fy  * ((1.0f - fx) * r1[ix0] + fx * r1[ix1]);
            } else {
                int y = ys0 + ry;
                float sy = fminf(fmaxf(((float)y - (float)y0 + 0.5f) * scy - 0.5f, 0.0f), 27.0f);
                float sx = fminf(fmaxf(((float)x - (float)x0 + 0.5f) * scx - 0.5f, 0.0f), 27.0f);
                val = bilin_ref(lg, sx, sy);
            }
            on = (val > 0.0f);
        }
        unsigned int bits = __ballot_sync(0xffffffffu, on);
        if (lane == 0) {
            if (fits) g_bits[i][ry * nwx + (xw - xw0)] = bits;
            lm += __popc(bits);
        }
    }
    if (lane == 0 && lm) atomicAdd(&s_cnt, lm);
    __syncthreads();
    if (threadIdx.x == 0) g_msumP[i][blockIdx.y] = s_cnt;
}

// ---------------------------------------------------------------------------
__global__ __launch_bounds__(256) void k_scan(const float* __restrict__ rois,
                                              const float* __restrict__ prob,
                                              const int*   __restrict__ clsidx,
                                              const float* __restrict__ mask_prob,
                                              int N) {
    extern __shared__ unsigned int sm_mask[];               // IMG_H*WPR words
    __shared__ float sp[MAXN];
    __shared__ int   sord[MAXN];
    __shared__ int   scls[MAXN];
    __shared__ int   s_ovl, s_keep;
    __shared__ float lg[MM * MM];

    int c = blockIdx.x;
    int t = threadIdx.x;

    if (t < N) sp[t] = prob[t];
    __syncthreads();
    if (t < N) {
        float pi = sp[t];
        int r = 0;
        for (int j = 0; j < N; j++) {
            float pj = sp[j];
            r += (pj > pi) || (pj == pi && j < t);
        }
        sord[r] = t;
        scls[r] = clsidx[t] - 1;
    }
    __syncthreads();

    uint4* m4 = reinterpret_cast<uint4*>(sm_mask);
    uint4 z4 = make_uint4(0u, 0u, 0u, 0u);
    for (int w = t; w < (IMG_H * WPR) / 4; w += blockDim.x) m4[w] = z4;
    __syncthreads();

    for (int i = 0; i < N; i++) {
        if (scls[i] != c) continue;

        int msum = 0;
        #pragma unroll
        for (int u = 0; u < NSPLIT; u++) msum += g_msumP[i][u];
        if (msum == 0) { if (t == 0) g_keep[i] = 0; continue; }

        int o = sord[i];
        float4 rb = reinterpret_cast<const float4*>(rois)[o];
        int x0 = (int)rb.x, y0 = (int)rb.y, x1 = (int)rb.z, y1 = (int)rb.w;
        int xs0 = max(x0, 0), xs1 = min(x1 + 1, IMG_W);
        int ys0 = max(y0, 0), ys1 = min(y1 + 1, IMG_H);
        int bh = ys1 - ys0;

        int xw0 = xs0 >> 5, xw1 = (xs1 + 31) >> 5;
        int nwx = xw1 - xw0;
        int total = nwx * bh;
        bool fits = (total <= BITSW);

        if (t == 0) s_ovl = 0;
        __syncthreads();

        int lo = 0;
        if (fits) {
            const unsigned int* bi = g_bits[i];
            for (int k = t; k < total; k += blockDim.x) {
                unsigned int b = bi[k];
                if (b) {
                    int ry = k / nwx;
                    int xw = xw0 + (k - ry * nwx);
                    lo += __popc(b & sm_mask[(ys0 + ry) * WPR + xw]);
                }
            }
        } else {
            const float* lp = mask_prob + (long long)o * (MM * MM);
            for (int u = t; u < MM * MM; u += blockDim.x) lg[u] = lp[u];
            __syncthreads();
            float wv = fmaxf((float)(x1 - x0 + 1), 1.0f);
            float hv = fmaxf((float)(y1 - y0 + 1), 1.0f);
            float scx = 28.0f / wv, scy = 28.0f / hv;
            for (int k = t; k < total; k += blockDim.x) {
                int ry = k / nwx;
                int y  = ys0 + ry;
                int xw = xw0 + (k - ry * nwx);
                unsigned int cw = sm_mask[y * WPR + xw];
                if (!cw) continue;
                float sy = fminf(fmaxf(((float)y - (float)y0 + 0.5f) * scy - 0.5f, 0.0f), 27.0f);
                int xlo2 = max(xs0, xw << 5);
                int xhi2 = min(xs1, (xw << 5) + 32);
                for (int x = xlo2; x < xhi2; x++) {
                    if (cw & (1u << (x & 31))) {
                        float sx = fminf(fmaxf(((float)x - (float)x0 + 0.5f) * scx - 0.5f, 0.0f), 27.0f);
                        if (bilin_ref(lg, sx, sy) > 0.0f) lo++;
                    }
                }
            }
        }
        #pragma unroll
        for (int off = 16; off > 0; off >>= 1)
            lo += __shfl_down_sync(0xffffffffu, lo, off);
        if ((t & 31) == 0 && lo) atomicAdd(&s_ovl, lo);
        __syncthreads();

        if (t == 0) {
            int kp = ((float)s_ovl <= 0.3f * (float)msum);
            s_keep = kp;
            g_keep[i] = kp;
        }
        __syncthreads();

        if (s_keep) {
            if (fits) {
                const unsigned int* bi = g_bits[i];
                for (int k = t; k < total; k += blockDim.x) {
                    unsigned int b = bi[k];        // L2-hot re-read
                    if (b) {
                        int ry = k / nwx;
                        int xw = xw0 + (k - ry * nwx);
                        sm_mask[(ys0 + ry) * WPR + xw] |= b;
                    }
                }
            } else {
                float wv = fmaxf((float)(x1 - x0 + 1), 1.0f);
                float hv = fmaxf((float)(y1 - y0 + 1), 1.0f);
                float scx = 28.0f / wv, scy = 28.0f / hv;
                for (int k = t; k < total; k += blockDim.x) {
                    int ry = k / nwx;
                    int y  = ys0 + ry;
                    int xw = xw0 + (k - ry * nwx);
                    float sy = fminf(fmaxf(((float)y - (float)y0 + 0.5f) * scy - 0.5f, 0.0f), 27.0f);
                    int xlo2 = max(xs0, xw << 5);
                    int xhi2 = min(xs1, (xw << 5) + 32);
                    unsigned int bits = 0u;
                    for (int x = xlo2; x < xhi2; x++) {
                        float sx = fminf(fmaxf(((float)x - (float)x0 + 0.5f) * scx - 0.5f, 0.0f), 27.0f);
                        if (bilin_ref(lg, sx, sy) > 0.0f) bits |= (1u << (x & 31));
                    }
                    if (bits) sm_mask[y * WPR + xw] |= bits;
                }
            }
        }
        __syncthreads();
    }
}

// ---------------------------------------------------------------------------
// grid (N+1, NSPLIT): CTAs [0,N) paste a y-slice; CTA N writes keep_inds.
__global__ __launch_bounds__(256) void k_paste(const float* __restrict__ rois,
                                               const float* __restrict__ prob,
                                               const float* __restrict__ mask_prob,
                                               float* __restrict__ out_keep,
                                               float* __restrict__ energy,
                                               int N, int has_keep) {
    __shared__ float sp[MAXN];
    __shared__ int   sord[MAXN];
    __shared__ int   kv[MAXN];
    __shared__ int   pf[MAXN];
    __shared__ float lg[MM * MM];
    __shared__ int   s_ix0[BOXMAX], s_ix1[BOXMAX];
    __shared__ float s_fx[BOXMAX];

    int t = threadIdx.x;
    stage_sort(prob, N, sp, sord);

    if (t < MAXN) {
        int k = (t < N) ? g_keep[t] : 0;
        kv[t] = k;
        pf[t] = k;
    }
    __syncthreads();
    #pragma unroll
    for (int off = 1; off < MAXN; off <<= 1) {
        int v = (t < MAXN && t >= off) ? pf[t - off] : 0;
        __syncthreads();
        if (t < MAXN) pf[t] += v;
        __syncthreads();
    }

    int i = blockIdx.x;
    if (i >= N) {
        if (blockIdx.y != 0 || !has_keep) return;
        int nk = pf[N - 1];
        if (t < N) {
            if (kv[t]) out_keep[pf[t] - 1] = (float)sord[t];
            if (t >= nk) out_keep[t] = -1.0f;
        }
        return;
    }

    if (!kv[i]) return;
    int slot = pf[i] - 1;

    int o = sord[i];
    float4 rb = reinterpret_cast<const float4*>(rois)[o];
    int x0 = (int)rb.x, y0 = (int)rb.y, x1 = (int)rb.z, y1 = (int)rb.w;
    int xs0 = max(x0, 0), xs1 = min(x1 + 1, IMG_W);
    int ys0 = max(y0, 0), ys1 = min(y1 + 1, IMG_H);
    int bw = xs1 - xs0, bh = ys1 - ys0;
    if (bw <= 0 || bh <= 0) return;

    const float* lp = mask_prob + (long long)o * (MM * MM);
    for (int u = t; u < MM * MM; u += blockDim.x) lg[u] = lp[u];

    float wv = fmaxf((float)(x1 - x0 + 1), 1.0f);
    float hv = fmaxf((float)(y1 - y0 + 1), 1.0f);
    float scx = 28.0f / wv, scy = 28.0f / hv;

    bool pre = (bw <= BOXMAX);
    if (pre) {
        for (int u = t; u < bw; u += blockDim.x) {
            float sx = fminf(fmaxf(((float)(xs0 + u) - (float)x0 + 0.5f) * scx - 0.5f, 0.0f), 27.0f);
            int ix0 = (int)sx;
            s_ix0[u] = ix0;
            s_ix1[u] = min(ix0 + 1, MM - 1);
            s_fx[u]  = sx - (float)ix0;
        }
    }
    __syncthreads();

    int chunk = (bh + NSPLIT - 1) / NSPLIT;
    int ry0   = blockIdx.y * chunk;
    int rows  = min(chunk, bh - ry0);
    if (rows <= 0) return;

    float* base = energy + (long long)slot * IMG_H * IMG_W;
    int total = bw * rows;
    for (int k = t; k < total; k += blockDim.x) {
        int q  = k / bw;
        int ry = ry0 + q;
        int rx = k - q * bw;
        int y = ys0 + ry, x = xs0 + rx;
        float sy = fminf(fmaxf(((float)y - (float)y0 + 0.5f) * scy - 0.5f, 0.0f), 27.0f);
        float val;
        if (pre) {
            int iy0 = (int)sy;
            int iy1 = min(iy0 + 1, MM - 1);
            float fy = sy - (float)iy0;
            const float* r0 = lg + iy0 * MM;
            const float* r1 = lg + iy1 * MM;
            int ix0 = s_ix0[rx], ix1 = s_ix1[rx];
            float fx = s_fx[rx];
            val = (1.0f - fy) * ((1.0f - fx) * r0[ix0] + fx * r0[ix1])
                +         fy  * ((1.0f - fx) * r1[ix0] + fx * r1[ix1]);
        } else {
            float sx = fminf(fmaxf(((float)x - (float)x0 + 0.5f) * scx - 0.5f, 0.0f), 27.0f);
            val = bilin_ref(lg, sx, sy);
        }
        base[y * IMG_W + x] = val;
    }
}

// ---------------------------------------------------------------------------
extern "C" void kernel_launch(void* const* d_in, const int* in_sizes, int n_in,
                              void* d_out, int out_size) {
    const float* rois  = (const float*)d_in[0];
    const float* prob  = (const float*)d_in[1];
    const float* mp    = (const float*)d_in[2];
    const int*   cidx  = (const int*)d_in[3];

    int N = in_sizes[1];
    if (N > MAXN) N = MAXN;

    float* out = (float*)d_out;
    long long HW = (long long)IMG_H * IMG_W;
    int has_keep = ((long long)out_size == (long long)N + (long long)N * HW) ? 1 : 0;
    float* energy = out + (has_keep ? N : 0);

    static cudaStream_t s_side = nullptr;
    static cudaEvent_t ev_fork = nullptr, ev_join = nullptr;
    static bool attr_set = false;
    if (!s_side) {
        cudaStreamCreateWithFlags(&s_side, cudaStreamNonBlocking);
        cudaEventCreateWithFlags(&ev_fork, cudaEventDisableTiming);
        cudaEventCreateWithFlags(&ev_join, cudaEventDisableTiming);
    }
    if (!attr_set) {
        cudaFuncSetAttribute(k_scan, cudaFuncAttributeMaxDynamicSharedMemorySize,
                             CMASK_BYTES);
        attr_set = true;
    }

    // fork: 256MB memset overlaps the decision chain
    cudaEventRecord(ev_fork, 0);
    cudaStreamWaitEvent(s_side, ev_fork, 0);
    cudaMemsetAsync(energy, 0, (size_t)N * HW * sizeof(float), s_side);
    cudaEventRecord(ev_join, s_side);

    k_bits<<<dim3(N, NSPLIT), 256>>>(rois, prob, mp, N);
    k_scan<<<NCLS, 256, CMASK_BYTES>>>(rois, prob, cidx, mp, N);

    cudaStreamWaitEvent(0, ev_join, 0);
    k_paste<<<dim3(N + 1, NSPLIT), 256>>>(rois, prob, mp, out, energy, N, has_keep);
}

// round 7
// speedup vs baseline: 1.8879x; 1.0945x over previous
#include <cuda_runtime.h>

// ---------------------------------------------------------------------------
// MaskRemoval — R7: issue-rate fix for raster kernels (warp-per-row + shfl).
//   memset  : 256MB zero on side stream (overlaps bits+scan)
//   k_bits  : grid (N,8); warp per box row; logit rows in registers,
//             bilinear corners via shfl; ballot -> g_bits + popcounts
//   k_scan  : grid (NCLS); class mask in 80KB dyn smem; popc + OR merge
//   k_paste : grid (N+1,8); same row structure; CTA N writes keep_inds
// ---------------------------------------------------------------------------

#define MAXN   128
#define NCLS   80
#define MM     28
#define IMG_H  800
#define IMG_W  800
#define WPR    25                      // 800/32 words per image row
#define BOXMAX 384
#define NSPLIT 8                       // y-slices per ROI for raster kernels
#define BITSW  8192                    // words of bit-scratch per ROI
#define CMASK_BYTES (IMG_H * WPR * 4)  // 80000 B dynamic smem for k_scan

__device__ int g_keep[MAXN];
__device__ int g_msumP[MAXN][NSPLIT];            // per-slice popcounts
__device__ unsigned int g_bits[MAXN][BITSW];     // 4 MB ROI bit rasters

// exact reference bilinear form (keep decision thresholds on val>0)
__device__ __forceinline__ float bilin_ref(const float* lg, float sx, float sy) {
    int ix0 = (int)sx;
    int iy0 = (int)sy;
    int ix1 = min(ix0 + 1, MM - 1);
    int iy1 = min(iy0 + 1, MM - 1);
    float fx = sx - (float)ix0;
    float fy = sy - (float)iy0;
    float v00 = lg[iy0 * MM + ix0], v01 = lg[iy0 * MM + ix1];
    float v10 = lg[iy1 * MM + ix0], v11 = lg[iy1 * MM + ix1];
    return (1.0f - fy) * ((1.0f - fx) * v00 + fx * v01)
         +         fy  * ((1.0f - fx) * v10 + fx * v11);
}

// stable descending rank sort into smem: sord[rank] = original index
__device__ __forceinline__ void stage_sort(const float* __restrict__ prob,
                                           int N, float* sp, int* sord) {
    int t = threadIdx.x;
    if (t < N) sp[t] = prob[t];
    __syncthreads();
    if (t < N) {
        float pi = sp[t];
        int r = 0;
        for (int j = 0; j < N; j++) {
            float pj = sp[j];
            r += (pj > pi) || (pj == pi && j < t);
        }
        sord[r] = t;
    }
    __syncthreads();
}

// ---------------------------------------------------------------------------
__global__ __launch_bounds__(256) void k_bits(const float* __restrict__ rois,
                                              const float* __restrict__ prob,
                                              const float* __restrict__ mask_prob,
                                              int N) {
    __shared__ float sp[MAXN];
    __shared__ int   sord[MAXN];
    __shared__ float lg[MM * MM];
    __shared__ float2 s_cx[BOXMAX];    // (fx, ix0-as-float-bits) per box column
    __shared__ int   s_cnt;

    int i = blockIdx.x;
    if (i >= N) return;
    stage_sort(prob, N, sp, sord);

    int o = sord[i];
    float4 rb = reinterpret_cast<const float4*>(rois)[o];
    int x0 = (int)rb.x, y0 = (int)rb.y, x1 = (int)rb.z, y1 = (int)rb.w;
    int xs0 = max(x0, 0), xs1 = min(x1 + 1, IMG_W);
    int ys0 = max(y0, 0), ys1 = min(y1 + 1, IMG_H);
    int bw = xs1 - xs0, bh = ys1 - ys0;
    if (bw <= 0 || bh <= 0) return;        // g_msumP slot never written => 0

    if (threadIdx.x == 0) s_cnt = 0;
    const float* lp = mask_prob + (long long)o * (MM * MM);
    for (int t = threadIdx.x; t < MM * MM; t += blockDim.x) lg[t] = lp[t];

    float wv = fmaxf((float)(x1 - x0 + 1), 1.0f);
    float hv = fmaxf((float)(y1 - y0 + 1), 1.0f);
    float scx = 28.0f / wv, scy = 28.0f / hv;

    bool pre = (bw <= BOXMAX);
    if (pre) {
        for (int t = threadIdx.x; t < bw; t += blockDim.x) {
            float sx = fminf(fmaxf(((float)(xs0 + t) - (float)x0 + 0.5f) * scx - 0.5f, 0.0f), 27.0f);
            int ix0 = (int)sx;
            s_cx[t] = make_float2(sx - (float)ix0, __int_as_float(ix0));
        }
    }
    __syncthreads();

    int chunk = (bh + NSPLIT - 1) / NSPLIT;
    int ry0   = blockIdx.y * chunk;
    int rows  = min(chunk, bh - ry0);
    if (rows <= 0) return;

    int xw0 = xs0 >> 5, xw1 = (xs1 + 31) >> 5;
    int nwx = xw1 - xw0;
    bool fits = (nwx * bh <= BITSW);

    int warp = threadIdx.x >> 5;
    int lane = threadIdx.x & 31;
    int nwarps = blockDim.x >> 5;
    int lm = 0;

    for (int r = warp; r < rows; r += nwarps) {
        int ry = ry0 + r;
        int y  = ys0 + ry;
        float sy = fminf(fmaxf(((float)y - (float)y0 + 0.5f) * scy - 0.5f, 0.0f), 27.0f);
        int iy0 = (int)sy;
        int iy1 = min(iy0 + 1, MM - 1);
        float fy = sy - (float)iy0;
        // logit rows into registers (lanes 0..27 valid; shfl never targets 28+)
        int ll = min(lane, MM - 1);
        float r0v = lg[iy0 * MM + ll];
        float r1v = lg[iy1 * MM + ll];

        unsigned int* dst = fits ? &g_bits[i][ry * nwx] : nullptr;
        for (int xw = xw0; xw < xw1; xw++) {
            int x = (xw << 5) + lane;
            bool inb = (x >= xs0) && (x < xs1);
            float val;
            if (pre) {
                float2 cf = s_cx[inb ? (x - xs0) : 0];
                float fx = cf.x;
                int ix0 = __float_as_int(cf.y);
                int ix1 = min(ix0 + 1, MM - 1);
                float v00 = __shfl_sync(0xffffffffu, r0v, ix0);
                float v01 = __shfl_sync(0xffffffffu, r0v, ix1);
                float v10 = __shfl_sync(0xffffffffu, r1v, ix0);
                float v11 = __shfl_sync(0xffffffffu, r1v, ix1);
                val = (1.0f - fy) * ((1.0f - fx) * v00 + fx * v01)
                    +         fy  * ((1.0f - fx) * v10 + fx * v11);
            } else {
                float sx = fminf(fmaxf(((float)x - (float)x0 + 0.5f) * scx - 0.5f, 0.0f), 27.0f);
                val = bilin_ref(lg, sx, sy);
            }
            bool on = inb && (val > 0.0f);
            unsigned int bits = __ballot_sync(0xffffffffu, on);
            if (lane == 0) {
                if (dst) dst[xw - xw0] = bits;
                lm += __popc(bits);
            }
        }
    }
    if (lane == 0 && lm) atomicAdd(&s_cnt, lm);
    __syncthreads();
    if (threadIdx.x == 0) g_msumP[i][blockIdx.y] = s_cnt;
}

// ---------------------------------------------------------------------------
__global__ __launch_bounds__(256) void k_scan(const float* __restrict__ rois,
                                              const float* __restrict__ prob,
                                              const int*   __restrict__ clsidx,
                                              const float* __restrict__ mask_prob,
                                              int N) {
    extern __shared__ unsigned int sm_mask[];               // IMG_H*WPR words
    __shared__ float sp[MAXN];
    __shared__ int   sord[MAXN];
    __shared__ int   scls[MAXN];
    __shared__ int   s_ovl, s_keep;
    __shared__ float lg[MM * MM];

    int c = blockIdx.x;
    int t = threadIdx.x;

    if (t < N) sp[t] = prob[t];
    __syncthreads();
    if (t < N) {
        float pi = sp[t];
        int r = 0;
        for (int j = 0; j < N; j++) {
            float pj = sp[j];
            r += (pj > pi) || (pj == pi && j < t);
        }
        sord[r] = t;
        scls[r] = clsidx[t] - 1;
    }
    __syncthreads();

    uint4* m4 = reinterpret_cast<uint4*>(sm_mask);
    uint4 z4 = make_uint4(0u, 0u, 0u, 0u);
    for (int w = t; w < (IMG_H * WPR) / 4; w += blockDim.x) m4[w] = z4;
    __syncthreads();

    for (int i = 0; i < N; i++) {
        if (scls[i] != c) continue;

        int msum = 0;
        #pragma unroll
        for (int u = 0; u < NSPLIT; u++) msum += g_msumP[i][u];
        if (msum == 0) { if (t == 0) g_keep[i] = 0; continue; }

        int o = sord[i];
        float4 rb = reinterpret_cast<const float4*>(rois)[o];
        int x0 = (int)rb.x, y0 = (int)rb.y, x1 = (int)rb.z, y1 = (int)rb.w;
        int xs0 = max(x0, 0), xs1 = min(x1 + 1, IMG_W);
        int ys0 = max(y0, 0), ys1 = min(y1 + 1, IMG_H);
        int bh = ys1 - ys0;

        int xw0 = xs0 >> 5, xw1 = (xs1 + 31) >> 5;
        int nwx = xw1 - xw0;
        int total = nwx * bh;
        bool fits = (total <= BITSW);

        if (t == 0) s_ovl = 0;
        __syncthreads();

        int lo = 0;
        if (fits) {
            const unsigned int* bi = g_bits[i];
            for (int k = t; k < total; k += blockDim.x) {
                unsigned int b = bi[k];
                if (b) {
                    int ry = k / nwx;
                    int xw = xw0 + (k - ry * nwx);
                    lo += __popc(b & sm_mask[(ys0 + ry) * WPR + xw]);
                }
            }
        } else {
            const float* lp = mask_prob + (long long)o * (MM * MM);
            for (int u = t; u < MM * MM; u += blockDim.x) lg[u] = lp[u];
            __syncthreads();
            float wv = fmaxf((float)(x1 - x0 + 1), 1.0f);
            float hv = fmaxf((float)(y1 - y0 + 1), 1.0f);
            float scx = 28.0f / wv, scy = 28.0f / hv;
            for (int k = t; k < total; k += blockDim.x) {
                int ry = k / nwx;
                int y  = ys0 + ry;
                int xw = xw0 + (k - ry * nwx);
                unsigned int cw = sm_mask[y * WPR + xw];
                if (!cw) continue;
                float sy = fminf(fmaxf(((float)y - (float)y0 + 0.5f) * scy - 0.5f, 0.0f), 27.0f);
                int xlo2 = max(xs0, xw << 5);
                int xhi2 = min(xs1, (xw << 5) + 32);
                for (int x = xlo2; x < xhi2; x++) {
                    if (cw & (1u << (x & 31))) {
                        float sx = fminf(fmaxf(((float)x - (float)x0 + 0.5f) * scx - 0.5f, 0.0f), 27.0f);
                        if (bilin_ref(lg, sx, sy) > 0.0f) lo++;
                    }
                }
            }
        }
        #pragma unroll
        for (int off = 16; off > 0; off >>= 1)
            lo += __shfl_down_sync(0xffffffffu, lo, off);
        if ((t & 31) == 0 && lo) atomicAdd(&s_ovl, lo);
        __syncthreads();

        if (t == 0) {
            int kp = ((float)s_ovl <= 0.3f * (float)msum);
            s_keep = kp;
            g_keep[i] = kp;
        }
        __syncthreads();

        if (s_keep) {
            if (fits) {
                const unsigned int* bi = g_bits[i];
                for (int k = t; k < total; k += blockDim.x) {
                    unsigned int b = bi[k];        // L2-hot re-read
                    if (b) {
                        int ry = k / nwx;
                        int xw = xw0 + (k - ry * nwx);
                        sm_mask[(ys0 + ry) * WPR + xw] |= b;
                    }
                }
            } else {
                float wv = fmaxf((float)(x1 - x0 + 1), 1.0f);
                float hv = fmaxf((float)(y1 - y0 + 1), 1.0f);
                float scx = 28.0f / wv, scy = 28.0f / hv;
                for (int k = t; k < total; k += blockDim.x) {
                    int ry = k / nwx;
                    int y  = ys0 + ry;
                    int xw = xw0 + (k - ry * nwx);
                    float sy = fminf(fmaxf(((float)y - (float)y0 + 0.5f) * scy - 0.5f, 0.0f), 27.0f);
                    int xlo2 = max(xs0, xw << 5);
                    int xhi2 = min(xs1, (xw << 5) + 32);
                    unsigned int bits = 0u;
                    for (int x = xlo2; x < xhi2; x++) {
                        float sx = fminf(fmaxf(((float)x - (float)x0 + 0.5f) * scx - 0.5f, 0.0f), 27.0f);
                        if (bilin_ref(lg, sx, sy) > 0.0f) bits |= (1u << (x & 31));
                    }
                    if (bits) sm_mask[y * WPR + xw] |= bits;
                }
            }
        }
        __syncthreads();
    }
}

// ---------------------------------------------------------------------------
// grid (N+1, NSPLIT): CTAs [0,N) paste a y-slice; CTA N writes keep_inds.
__global__ __launch_bounds__(256) void k_paste(const float* __restrict__ rois,
                                               const float* __restrict__ prob,
                                               const float* __restrict__ mask_prob,
                                               float* __restrict__ out_keep,
                                               float* __restrict__ energy,
                                               int N, int has_keep) {
    __shared__ float sp[MAXN];
    __shared__ int   sord[MAXN];
    __shared__ int   kv[MAXN];
    __shared__ int   pf[MAXN];
    __shared__ float lg[MM * MM];
    __shared__ float2 s_cx[BOXMAX];

    int t = threadIdx.x;
    stage_sort(prob, N, sp, sord);

    if (t < MAXN) {
        int k = (t < N) ? g_keep[t] : 0;
        kv[t] = k;
        pf[t] = k;
    }
    __syncthreads();
    #pragma unroll
    for (int off = 1; off < MAXN; off <<= 1) {
        int v = (t < MAXN && t >= off) ? pf[t - off] : 0;
        __syncthreads();
        if (t < MAXN) pf[t] += v;
        __syncthreads();
    }

    int i = blockIdx.x;
    if (i >= N) {
        if (blockIdx.y != 0 || !has_keep) return;
        int nk = pf[N - 1];
        if (t < N) {
            if (kv[t]) out_keep[pf[t] - 1] = (float)sord[t];
            if (t >= nk) out_keep[t] = -1.0f;
        }
        return;
    }

    if (!kv[i]) return;
    int slot = pf[i] - 1;

    int o = sord[i];
    float4 rb = reinterpret_cast<const float4*>(rois)[o];
    int x0 = (int)rb.x, y0 = (int)rb.y, x1 = (int)rb.z, y1 = (int)rb.w;
    int xs0 = max(x0, 0), xs1 = min(x1 + 1, IMG_W);
    int ys0 = max(y0, 0), ys1 = min(y1 + 1, IMG_H);
    int bw = xs1 - xs0, bh = ys1 - ys0;
    if (bw <= 0 || bh <= 0) return;

    const float* lp = mask_prob + (long long)o * (MM * MM);
    for (int u = t; u < MM * MM; u += blockDim.x) lg[u] = lp[u];

    float wv = fmaxf((float)(x1 - x0 + 1), 1.0f);
    float hv = fmaxf((float)(y1 - y0 + 1), 1.0f);
    float scx = 28.0f / wv, scy = 28.0f / hv;

    bool pre = (bw <= BOXMAX);
    if (pre) {
        for (int u = t; u < bw; u += blockDim.x) {
            float sx = fminf(fmaxf(((float)(xs0 + u) - (float)x0 + 0.5f) * scx - 0.5f, 0.0f), 27.0f);
            int ix0 = (int)sx;
            s_cx[u] = make_float2(sx - (float)ix0, __int_as_float(ix0));
        }
    }
    __syncthreads();

    int chunk = (bh + NSPLIT - 1) / NSPLIT;
    int ry0   = blockIdx.y * chunk;
    int rows  = min(chunk, bh - ry0);
    if (rows <= 0) return;

    int xw0 = xs0 >> 5, xw1 = (xs1 + 31) >> 5;
    int warp = t >> 5;
    int lane = t & 31;
    int nwarps = blockDim.x >> 5;

    float* base = energy + (long long)slot * IMG_H * IMG_W;

    for (int r = warp; r < rows; r += nwarps) {
        int ry = ry0 + r;
        int y  = ys0 + ry;
        float sy = fminf(fmaxf(((float)y - (float)y0 + 0.5f) * scy - 0.5f, 0.0f), 27.0f);
        int iy0 = (int)sy;
        int iy1 = min(iy0 + 1, MM - 1);
        float fy = sy - (float)iy0;
        int ll = min(lane, MM - 1);
        float r0v = lg[iy0 * MM + ll];
        float r1v = lg[iy1 * MM + ll];
        float* rowp = base + y * IMG_W;

        for (int xw = xw0; xw < xw1; xw++) {
            int x = (xw << 5) + lane;
            bool inb = (x >= xs0) && (x < xs1);
            float val;
            if (pre) {
                float2 cf = s_cx[inb ? (x - xs0) : 0];
                float fx = cf.x;
                int ix0 = __float_as_int(cf.y);
                int ix1 = min(ix0 + 1, MM - 1);
                float v00 = __shfl_sync(0xffffffffu, r0v, ix0);
                float v01 = __shfl_sync(0xffffffffu, r0v, ix1);
                float v10 = __shfl_sync(0xffffffffu, r1v, ix0);
                float v11 = __shfl_sync(0xffffffffu, r1v, ix1);
                val = (1.0f - fy) * ((1.0f - fx) * v00 + fx * v01)
                    +         fy  * ((1.0f - fx) * v10 + fx * v11);
            } else {
                float sx = fminf(fmaxf(((float)x - (float)x0 + 0.5f) * scx - 0.5f, 0.0f), 27.0f);
                val = bilin_ref(lg, sx, sy);
            }
            if (inb) rowp[x] = val;
        }
    }
}

// ---------------------------------------------------------------------------
extern "C" void kernel_launch(void* const* d_in, const int* in_sizes, int n_in,
                              void* d_out, int out_size) {
    const float* rois  = (const float*)d_in[0];
    const float* prob  = (const float*)d_in[1];
    const float* mp    = (const float*)d_in[2];
    const int*   cidx  = (const int*)d_in[3];

    int N = in_sizes[1];
    if (N > MAXN) N = MAXN;

    float* out = (float*)d_out;
    long long HW = (long long)IMG_H * IMG_W;
    int has_keep = ((long long)out_size == (long long)N + (long long)N * HW) ? 1 : 0;
    float* energy = out + (has_keep ? N : 0);

    static cudaStream_t s_side = nullptr;
    static cudaEvent_t ev_fork = nullptr, ev_join = nullptr;
    static bool attr_set = false;
    if (!s_side) {
        cudaStreamCreateWithFlags(&s_side, cudaStreamNonBlocking);
        cudaEventCreateWithFlags(&ev_fork, cudaEventDisableTiming);
        cudaEventCreateWithFlags(&ev_join, cudaEventDisableTiming);
    }
    if (!attr_set) {
        cudaFuncSetAttribute(k_scan, cudaFuncAttributeMaxDynamicSharedMemorySize,
                             CMASK_BYTES);
        attr_set = true;
    }

    // fork: 256MB memset overlaps the decision chain
    cudaEventRecord(ev_fork, 0);
    cudaStreamWaitEvent(s_side, ev_fork, 0);
    cudaMemsetAsync(energy, 0, (size_t)N * HW * sizeof(float), s_side);
    cudaEventRecord(ev_join, s_side);

    k_bits<<<dim3(N, NSPLIT), 256>>>(rois, prob, mp, N);
    k_scan<<<NCLS, 256, CMASK_BYTES>>>(rois, prob, cidx, mp, N);

    cudaStreamWaitEvent(0, ev_join, 0);
    k_paste<<<dim3(N + 1, NSPLIT), 256>>>(rois, prob, mp, out, energy, N, has_keep);
}